// round 1
// baseline (speedup 1.0000x reference)
#include <cuda_runtime.h>

#define KDIM 64
#define CDIM 128
#define MAXSPLIT 160

// Scratch (no allocs allowed): split-N partials + reduced U/V + P/R
__device__ float g_part[2][MAXSPLIT][KDIM][CDIM];   // ~10.5 MB
__device__ float g_UV[2][KDIM][CDIM];
__device__ float g_PR[2][KDIM][CDIM];

// ---------------------------------------------------------------------------
// Kernel 1: partial U/V over a 64-row slice of N.
//   U[k,c] = sum_n Qr[n,k]*re[n,c] + Qi[n,k]*im[n,c]
//   V[k,c] = sum_n Qi[n,k]*re[n,c] - Qr[n,k]*im[n,c]
// grid (nsplit, 2 c-halves), block (16,16); thread = 4k x 4c micro-tile.
// ---------------------------------------------------------------------------
__global__ __launch_bounds__(256) void k1_partial(
    const float* __restrict__ Qr, const float* __restrict__ Qi,
    const float* __restrict__ re, const float* __restrict__ im, int N)
{
    __shared__ float sQr[32 * 64];
    __shared__ float sQi[32 * 64];
    __shared__ float sRe[32 * 64];
    __shared__ float sIm[32 * 64];

    const int s  = blockIdx.x;
    const int c0 = blockIdx.y * 64;
    const int n0 = s * 64;
    const int tx = threadIdx.x, ty = threadIdx.y;
    const int tid = ty * 16 + tx;

    float u[4][4] = {};
    float v[4][4] = {};

    for (int rt = 0; rt < 64; rt += 32) {
        #pragma unroll
        for (int q = 0; q < 2; q++) {
            int f   = tid + 256 * q;          // 512 float4 per tile
            int row = f >> 4;                 // 16 float4 per 64-float row
            int c4  = (f & 15) * 4;
            int n   = n0 + rt + row;
            float4 z = make_float4(0.f, 0.f, 0.f, 0.f);
            float4 a = z, b = z, x = z, y = z;
            if (n < N) {
                a = *(const float4*)(Qr + (long)n * 64 + c4);
                b = *(const float4*)(Qi + (long)n * 64 + c4);
                x = *(const float4*)(re + (long)n * 128 + c0 + c4);
                y = *(const float4*)(im + (long)n * 128 + c0 + c4);
            }
            *(float4*)&sQr[row * 64 + c4] = a;
            *(float4*)&sQi[row * 64 + c4] = b;
            *(float4*)&sRe[row * 64 + c4] = x;
            *(float4*)&sIm[row * 64 + c4] = y;
        }
        __syncthreads();

        #pragma unroll 4
        for (int r = 0; r < 32; r++) {
            float4 q4 = *(float4*)&sQr[r * 64 + ty * 4];
            float4 g4 = *(float4*)&sQi[r * 64 + ty * 4];
            float4 x4 = *(float4*)&sRe[r * 64 + tx * 4];
            float4 y4 = *(float4*)&sIm[r * 64 + tx * 4];
            float qr[4] = {q4.x, q4.y, q4.z, q4.w};
            float qi[4] = {g4.x, g4.y, g4.z, g4.w};
            float xr[4] = {x4.x, x4.y, x4.z, x4.w};
            float xi[4] = {y4.x, y4.y, y4.z, y4.w};
            #pragma unroll
            for (int i = 0; i < 4; i++)
                #pragma unroll
                for (int j = 0; j < 4; j++) {
                    u[i][j] += qr[i] * xr[j] + qi[i] * xi[j];
                    v[i][j] += qi[i] * xr[j] - qr[i] * xi[j];
                }
        }
        __syncthreads();
    }

    #pragma unroll
    for (int i = 0; i < 4; i++) {
        int k = ty * 4 + i;
        *(float4*)&g_part[0][s][k][c0 + tx * 4] = make_float4(u[i][0], u[i][1], u[i][2], u[i][3]);
        *(float4*)&g_part[1][s][k][c0 + tx * 4] = make_float4(v[i][0], v[i][1], v[i][2], v[i][3]);
    }
}

// ---------------------------------------------------------------------------
// Kernel 2a: reduce partials over splits, scale row k by TT = Ritz[k]^long_diff
// 16384 threads, one per (uv,k,c).
// ---------------------------------------------------------------------------
__global__ void k2a_reduce(const float* __restrict__ Ritz,
                           const int* __restrict__ ldp, int nsplit)
{
    int t = blockIdx.x * blockDim.x + threadIdx.x;
    if (t >= 2 * KDIM * CDIM) return;
    int uv  = t / (KDIM * CDIM);
    int rem = t % (KDIM * CDIM);
    int k   = rem / CDIM;

    const float* p = &g_part[uv][0][0][0] + rem;
    float sum = 0.f;
    for (int s = 0; s < nsplit; s++) sum += p[(long)s * KDIM * CDIM];

    int ld = *ldp;
    float rz = Ritz[k];
    float tt = 1.f;
    for (int i = 0; i < ld; i++) tt *= rz;

    (&g_UV[0][0][0])[t] = tt * sum;
}

// ---------------------------------------------------------------------------
// Kernel 2b: P = U' @ W, R = V' @ W   ([64,128] @ [128,128])
// grid (2 matrices, 2 c'-halves), block (16,16), 4x4 micro-tile.
// ---------------------------------------------------------------------------
__global__ __launch_bounds__(256) void k2b_pr(const float* __restrict__ W)
{
    __shared__ float sA[64 * 68];   // [k][cc-chunk], pitch 68 (16B-aligned, bank-safe)
    __shared__ float sW[64 * 64];   // [cc-chunk][c']

    const int m   = blockIdx.x;
    const int cp0 = blockIdx.y * 64;
    const int tx = threadIdx.x, ty = threadIdx.y;
    const int tid = ty * 16 + tx;

    float acc[4][4] = {};

    for (int cc = 0; cc < 128; cc += 64) {
        #pragma unroll
        for (int q = 0; q < 4; q++) {
            int f   = tid + 256 * q;          // 1024 float4 per tile
            int row = f >> 4;
            int c4  = (f & 15) * 4;
            *(float4*)&sA[row * 68 + c4] = *(const float4*)&g_UV[m][row][cc + c4];
            *(float4*)&sW[row * 64 + c4] = *(const float4*)(W + (cc + row) * 128 + cp0 + c4);
        }
        __syncthreads();

        #pragma unroll 4
        for (int r = 0; r < 64; r++) {
            float a[4];
            #pragma unroll
            for (int i = 0; i < 4; i++) a[i] = sA[(ty * 4 + i) * 68 + r];
            float4 w4 = *(float4*)&sW[r * 64 + tx * 4];
            float wj[4] = {w4.x, w4.y, w4.z, w4.w};
            #pragma unroll
            for (int i = 0; i < 4; i++)
                #pragma unroll
                for (int j = 0; j < 4; j++)
                    acc[i][j] += a[i] * wj[j];
        }
        __syncthreads();
    }

    #pragma unroll
    for (int i = 0; i < 4; i++)
        *(float4*)&g_PR[m][ty * 4 + i][cp0 + tx * 4] =
            make_float4(acc[i][0], acc[i][1], acc[i][2], acc[i][3]);
}

// ---------------------------------------------------------------------------
// Kernel 3: res_real = Qr@P + Qi@R, res_imag = Qi@P - Qr@R, masked-ReLU add.
// grid (ceil(N/64), 2 c-halves), block (16,16), 4rows x 4cols micro-tile.
// ---------------------------------------------------------------------------
__global__ __launch_bounds__(256) void k3_out(
    const float* __restrict__ Qr, const float* __restrict__ Qi,
    const float* __restrict__ re, const float* __restrict__ im,
    float* __restrict__ out, int N)
{
    __shared__ float sQr[64 * 36];  // [row][k-chunk], pitch 36 (16B-aligned, bank-safe)
    __shared__ float sQi[64 * 36];
    __shared__ float sP [32 * 64];  // [k-chunk][c-tile]
    __shared__ float sR [32 * 64];

    const int n0 = blockIdx.x * 64;
    const int c0 = blockIdx.y * 64;
    const int tx = threadIdx.x, ty = threadIdx.y;
    const int tid = ty * 16 + tx;

    float sr[4][4] = {};
    float si[4][4] = {};

    for (int kk = 0; kk < 64; kk += 32) {
        // Q tiles: 64 rows x 32 k = 512 float4 each
        #pragma unroll
        for (int q = 0; q < 2; q++) {
            int f   = tid + 256 * q;
            int row = f >> 3;                 // 8 float4 per 32-float row
            int c4  = (f & 7) * 4;
            int n   = n0 + row;
            float4 a = make_float4(0.f, 0.f, 0.f, 0.f), b = a;
            if (n < N) {
                a = *(const float4*)(Qr + (long)n * 64 + kk + c4);
                b = *(const float4*)(Qi + (long)n * 64 + kk + c4);
            }
            *(float4*)&sQr[row * 36 + c4] = a;
            *(float4*)&sQi[row * 36 + c4] = b;
        }
        // P/R tiles: 32 k x 64 c = 512 float4 each
        #pragma unroll
        for (int q = 0; q < 2; q++) {
            int f   = tid + 256 * q;
            int row = f >> 4;
            int c4  = (f & 15) * 4;
            *(float4*)&sP[row * 64 + c4] = *(const float4*)&g_PR[0][kk + row][c0 + c4];
            *(float4*)&sR[row * 64 + c4] = *(const float4*)&g_PR[1][kk + row][c0 + c4];
        }
        __syncthreads();

        #pragma unroll 4
        for (int r = 0; r < 32; r++) {
            float qr[4], qi[4];
            #pragma unroll
            for (int i = 0; i < 4; i++) {
                qr[i] = sQr[(ty * 4 + i) * 36 + r];
                qi[i] = sQi[(ty * 4 + i) * 36 + r];
            }
            float4 p4 = *(float4*)&sP[r * 64 + tx * 4];
            float4 r4 = *(float4*)&sR[r * 64 + tx * 4];
            float pj[4] = {p4.x, p4.y, p4.z, p4.w};
            float rj[4] = {r4.x, r4.y, r4.z, r4.w};
            #pragma unroll
            for (int i = 0; i < 4; i++)
                #pragma unroll
                for (int j = 0; j < 4; j++) {
                    sr[i][j] += qr[i] * pj[j] + qi[i] * rj[j];
                    si[i][j] += qi[i] * pj[j] - qr[i] * rj[j];
                }
        }
        __syncthreads();
    }

    const long NC = (long)N * 128;
    #pragma unroll
    for (int i = 0; i < 4; i++) {
        int n = n0 + ty * 4 + i;
        if (n >= N) continue;
        long base = (long)n * 128 + c0 + tx * 4;
        float4 re4 = *(const float4*)(re + base);
        float4 im4 = *(const float4*)(im + base);
        float rl[4] = {re4.x, re4.y, re4.z, re4.w};
        float il[4] = {im4.x, im4.y, im4.z, im4.w};
        float orr[4], oii[4];
        #pragma unroll
        for (int j = 0; j < 4; j++) {
            float mask = (sr[i][j] >= 0.f) ? 1.f : 0.f;
            orr[j] = rl[j] + mask * sr[i][j];
            oii[j] = il[j] + mask * si[i][j];
        }
        *(float4*)(out + base)      = make_float4(orr[0], orr[1], orr[2], orr[3]);
        *(float4*)(out + NC + base) = make_float4(oii[0], oii[1], oii[2], oii[3]);
    }
}

// ---------------------------------------------------------------------------
extern "C" void kernel_launch(void* const* d_in, const int* in_sizes, int n_in,
                              void* d_out, int out_size)
{
    const float* real  = (const float*)d_in[0];
    const float* imag  = (const float*)d_in[1];
    const float* Qreal = (const float*)d_in[2];
    const float* Qimag = (const float*)d_in[3];
    const float* Ritz  = (const float*)d_in[4];
    const float* W     = (const float*)d_in[5];
    const int*   ldp   = (const int*)d_in[6];
    float* out = (float*)d_out;

    int N = in_sizes[0] / CDIM;
    int nsplit = (N + 63) / 64;   // 157 for N=10000, fits MAXSPLIT=160

    dim3 blk(16, 16);
    k1_partial<<<dim3(nsplit, 2), blk>>>(Qreal, Qimag, real, imag, N);
    k2a_reduce<<<64, 256>>>(Ritz, ldp, nsplit);
    k2b_pr<<<dim3(2, 2), blk>>>(W);
    k3_out<<<dim3((N + 63) / 64, 2), blk>>>(Qreal, Qimag, real, imag, out, N);
}